// round 14
// baseline (speedup 1.0000x reference)
#include <cuda_runtime.h>
#include <cstdint>

#define NART  50000
#define NCOMM 50000
#define FIN   768
#define PROJ  1024
#define HID   256
#define NOUT  128

// ---------------- scratch (device globals; no allocation allowed) ----------
__device__ __align__(16) float g_Wl12T[2 * PROJ * HID];   // [Wl1^T ; Wl2^T]  [512,1024]
__device__ __align__(16) float g_Wr1T [PROJ * HID];       // Wr1^T [256,1024]
__device__ __align__(16) float g_WaT12[2 * HID * FIN];    // ([W1@Wl1]^T ; [W1@Wl2]^T) [512,768]
__device__ __align__(16) float g_WCR  [2 * HID * FIN];    // ([W2@Wr1]^T ; Wr3^T)      [512,768]
__device__ __align__(16) float g_Wr2T [HID * HID];
__device__ __align__(16) float g_Wl3T [HID * HID];
__device__ __align__(16) float g_W3T  [NOUT * HID];
__device__ __align__(16) float g_ba12 [2 * HID];          // b1@Wl1 | b1@Wl2
__device__ __align__(16) float g_bcr  [2 * HID];          // b2@Wr1 | 0
__device__ __align__(16) float g_A12  [NART * 2 * HID];   // article proj: A1 | A2
__device__ __align__(16) float g_CR   [NCOMM * 2 * HID];  // community proj: C1 | R3
__device__ __align__(16) float g_AGG  [NCOMM * HID];
__device__ __align__(16) float g_CNT  [NCOMM];
__device__ __align__(16) float g_H1   [NCOMM * HID];      // h1, later h3
__device__ __align__(16) float g_H2   [NCOMM * HID];
__device__ __align__(16) float g_T    [NCOMM * HID];

__device__ __forceinline__ float f2tf32rna(float x) {
    uint32_t r;
    asm("cvt.rna.tf32.f32 %0, %1;" : "=r"(r) : "f"(x));
    return __uint_as_float(r);
}
__device__ __forceinline__ float4 tf32x4(float4 v) {
    v.x = f2tf32rna(v.x); v.y = f2tf32rna(v.y);
    v.z = f2tf32rna(v.z); v.w = f2tf32rna(v.w);
    return v;
}

// ---------------- tf32 mma.sync GEMM: C[M,N] = A[M,K] @ BT[N,K]^T (+bias) --
// 128x128 CTA tile, BK=32, 256 threads, warp tile 32x64 (2x8 m16n8k8).
// Static smem, register-prefetch double buffering, rna-rounded staging.
// __launch_bounds__(256,2): cap at 128 regs for 2 CTAs/SM (16 warps).
// Requires N%128==0, K%32==0; M guarded. grid = (N/128, ceil(M/128)).
#define PADK 36

__global__ void __launch_bounds__(256, 2) mmagemm(
    const float* __restrict__ A, const float* __restrict__ BT,
    const float* __restrict__ bias, float* __restrict__ C,
    int M, int N, int K)
{
    __shared__ float As[128][PADK];   // rows are 144B = 9*16B -> float4-aligned
    __shared__ float Bs[128][PADK];
    const int tid  = threadIdx.x;
    const int wid  = tid >> 5, lane = tid & 31;
    const int g    = lane >> 2, t = lane & 3;
    const int bm   = blockIdx.y * 128, bn = blockIdx.x * 128;
    const int wm   = (wid >> 1) * 32, wn = (wid & 1) * 64;

    float acc[2][8][4];
#pragma unroll
    for (int i = 0; i < 2; ++i)
#pragma unroll
        for (int j = 0; j < 8; ++j)
#pragma unroll
            for (int k = 0; k < 4; ++k) acc[i][j][k] = 0.f;

    // per-thread staging coords: 4 float4 segments each for A and B
    int mIdx[4], kqIdx[4];
#pragma unroll
    for (int s = 0; s < 4; ++s) {
        int i = s * 256 + tid;
        mIdx[s]  = i >> 3;          // 0..127
        kqIdx[s] = (i & 7) * 4;     // 0,4,...,28
    }

    const int nCh = K >> 5;
    float4 aReg[4], bReg[4];

    auto fetch = [&](int ci) {
#pragma unroll
        for (int s = 0; s < 4; ++s) {
            const int k0 = ci * 32 + kqIdx[s];
            const int am = bm + mIdx[s];
            aReg[s] = (am < M) ? *(const float4*)(A + (size_t)am * K + k0)
                               : make_float4(0.f, 0.f, 0.f, 0.f);
            bReg[s] = *(const float4*)(BT + (size_t)(bn + mIdx[s]) * K + k0);
        }
    };

    fetch(0);
    for (int ci = 0; ci < nCh; ++ci) {
#pragma unroll
        for (int s = 0; s < 4; ++s) {
            *(float4*)&As[mIdx[s]][kqIdx[s]] = tf32x4(aReg[s]);
            *(float4*)&Bs[mIdx[s]][kqIdx[s]] = tf32x4(bReg[s]);
        }
        __syncthreads();
        if (ci + 1 < nCh) fetch(ci + 1);   // overlap next LDG with MMA

#pragma unroll
        for (int kk = 0; kk < 32; kk += 8) {
            uint32_t aF[2][4], bF[8][2];
#pragma unroll
            for (int tm = 0; tm < 2; ++tm) {
                int r = wm + tm * 16 + g;
                aF[tm][0] = __float_as_uint(As[r][kk + t]);
                aF[tm][1] = __float_as_uint(As[r + 8][kk + t]);
                aF[tm][2] = __float_as_uint(As[r][kk + t + 4]);
                aF[tm][3] = __float_as_uint(As[r + 8][kk + t + 4]);
            }
#pragma unroll
            for (int tn = 0; tn < 8; ++tn) {
                int c = wn + tn * 8 + g;
                bF[tn][0] = __float_as_uint(Bs[c][kk + t]);
                bF[tn][1] = __float_as_uint(Bs[c][kk + t + 4]);
            }
#pragma unroll
            for (int tm = 0; tm < 2; ++tm)
#pragma unroll
                for (int tn = 0; tn < 8; ++tn)
                    asm volatile(
                        "mma.sync.aligned.m16n8k8.row.col.f32.tf32.tf32.f32 "
                        "{%0,%1,%2,%3}, {%4,%5,%6,%7}, {%8,%9}, {%0,%1,%2,%3};"
                        : "+f"(acc[tm][tn][0]), "+f"(acc[tm][tn][1]),
                          "+f"(acc[tm][tn][2]), "+f"(acc[tm][tn][3])
                        : "r"(aF[tm][0]), "r"(aF[tm][1]), "r"(aF[tm][2]), "r"(aF[tm][3]),
                          "r"(bF[tn][0]), "r"(bF[tn][1]));
        }
        __syncthreads();
    }

    // epilogue
#pragma unroll
    for (int tm = 0; tm < 2; ++tm)
#pragma unroll
        for (int half = 0; half < 2; ++half) {
            int row = bm + wm + tm * 16 + g + half * 8;
            if (row >= M) continue;
            float* cr = C + (size_t)row * N + bn + wn;
#pragma unroll
            for (int tn = 0; tn < 8; ++tn) {
                int col = tn * 8 + 2 * t;
                float2 v;
                v.x = acc[tm][tn][half * 2 + 0];
                v.y = acc[tm][tn][half * 2 + 1];
                if (bias) {
                    v.x += bias[bn + wn + col];
                    v.y += bias[bn + wn + col + 1];
                }
                *(float2*)(cr + col) = v;
            }
        }
}

// ---------------- fused prelude: all 7 weight transposes in one launch ------
__global__ void __launch_bounds__(256) transpose_all(
    const float* __restrict__ Wl1, const float* __restrict__ Wl2,
    const float* __restrict__ Wr1, const float* __restrict__ Wr3,
    const float* __restrict__ Wr2, const float* __restrict__ Wl3,
    const float* __restrict__ W3,
    float* __restrict__ Wl12T, float* __restrict__ Wr1T, float* __restrict__ WCR,
    float* __restrict__ Wr2T, float* __restrict__ Wl3T, float* __restrict__ W3T)
{
    int t = blockIdx.x * blockDim.x + threadIdx.x;
    const int S1 = PROJ * HID;   // 262144
    const int S4 = FIN * HID;    // 196608
    const int S5 = HID * HID;    // 65536
    const int S7 = HID * NOUT;   // 32768
    if (t < S1) {                                   // Wl1 -> Wl12T rows 0-255
        int r = t / HID, c = t % HID;
        Wl12T[(size_t)c * PROJ + r] = Wl1[t];
    } else if ((t -= S1) < S1) {                    // Wl2 -> Wl12T rows 256-511
        int r = t / HID, c = t % HID;
        Wl12T[S1 + (size_t)c * PROJ + r] = Wl2[t];
    } else if ((t -= S1) < S1) {                    // Wr1 -> Wr1T
        int r = t / HID, c = t % HID;
        Wr1T[(size_t)c * PROJ + r] = Wr1[t];
    } else if ((t -= S1) < S4) {                    // Wr3 -> WCR rows 256-511
        int r = t / HID, c = t % HID;
        WCR[(size_t)HID * FIN + (size_t)c * FIN + r] = Wr3[t];
    } else if ((t -= S4) < S5) {                    // Wr2 -> Wr2T
        int r = t / HID, c = t % HID;
        Wr2T[(size_t)c * HID + r] = Wr2[t];
    } else if ((t -= S5) < S5) {                    // Wl3 -> Wl3T
        int r = t / HID, c = t % HID;
        Wl3T[(size_t)c * HID + r] = Wl3[t];
    } else if ((t -= S5) < S7) {                    // W3 -> W3T
        int r = t / NOUT, c = t % NOUT;
        W3T[(size_t)c * HID + r] = W3[t];
    }
}
#define TRANS_TOTAL (3 * PROJ * HID + FIN * HID + 2 * HID * HID + HID * NOUT)

// ---------------- fused bias folds: 3 vec@mat in one launch -----------------
// grid (HID, 3). j=0: ba12[c]=b1·Wl1T[c]; j=1: ba12[HID+c]=b1·Wl2T[c];
// j=2: bcr[c]=b2·Wr1T[c] and bcr[HID+c]=0.
__global__ void __launch_bounds__(256) dotrow3_k(
    const float* __restrict__ b1, const float* __restrict__ b2,
    const float* __restrict__ Wl12T, const float* __restrict__ Wr1T,
    float* __restrict__ ba12, float* __restrict__ bcr)
{
    const int j = blockIdx.y, c = blockIdx.x, tid = threadIdx.x;
    const float* v;
    const float* row;
    float* out;
    if (j == 0)      { v = b1; row = Wl12T + (size_t)c * PROJ;         out = ba12 + c; }
    else if (j == 1) { v = b1; row = Wl12T + (size_t)(HID + c) * PROJ; out = ba12 + HID + c; }
    else             { v = b2; row = Wr1T  + (size_t)c * PROJ;         out = bcr + c;
                       if (tid == 0) bcr[HID + c] = 0.f; }
    float s = 0.f;
    for (int k = tid; k < PROJ; k += 256) s = fmaf(row[k], v[k], s);
#pragma unroll
    for (int o = 16; o > 0; o >>= 1) s += __shfl_xor_sync(0xFFFFFFFFu, s, o);
    __shared__ float red[8];
    if ((tid & 31) == 0) red[tid >> 5] = s;
    __syncthreads();
    if (tid == 0) {
        float r = red[0];
#pragma unroll
        for (int w = 1; w < 8; ++w) r += red[w];
        *out = r;
    }
}

// agg[dst,:HID] += feat[src*ld : +HID]; cnt[dst] += 1 (lane 0 of each edge).
// 64 threads/edge, one vector atomic per thread.
__global__ void scatter_k(const float* __restrict__ feat, int ld,
                          const int* __restrict__ src, const int* __restrict__ dst,
                          int E, float* __restrict__ agg, float* __restrict__ cnt)
{
    int tt = blockIdx.x * blockDim.x + threadIdx.x;
    int e = tt >> 6;
    if (e >= E) return;
    int c4 = (tt & 63) * 4;
    int d = dst[e];
    float4 v = *(const float4*)(feat + (size_t)src[e] * ld + c4);
    float4* o = (float4*)(agg + (size_t)d * HID + c4);
    atomicAdd(o, v);   // sm_90+: RED.E.ADD.F32.V4
    if ((tt & 63) == 0) atomicAdd(cnt + d, 1.0f);
}

// out = relu(agg/max(cnt,1) + bias + other)  (other has leading dim ldO)
__global__ void combine_k(const float* __restrict__ agg, const float* __restrict__ cnt,
                          const float* __restrict__ other, int ldO,
                          const float* __restrict__ bias, float* __restrict__ out)
{
    int t = blockIdx.x * blockDim.x + threadIdx.x;
    if (t >= NCOMM * (HID / 4)) return;
    int i = t >> 6;
    int c4 = (t & 63) * 4;
    float inv = 1.0f / fmaxf(cnt[i], 1.0f);
    float4 a = *(const float4*)(agg + (size_t)i * HID + c4);
    float4 o = *(const float4*)(other + (size_t)i * ldO + c4);
    float4 b = *(const float4*)(bias + c4);
    float4 r;
    r.x = fmaxf(fmaf(a.x, inv, o.x + b.x), 0.f);
    r.y = fmaxf(fmaf(a.y, inv, o.y + b.y), 0.f);
    r.z = fmaxf(fmaf(a.z, inv, o.z + b.z), 0.f);
    r.w = fmaxf(fmaf(a.w, inv, o.w + b.w), 0.f);
    *(float4*)(out + (size_t)i * HID + c4) = r;
}

// ---------------- launch ----------------------------------------------------
extern "C" void kernel_launch(void* const* d_in, const int* in_sizes, int n_in,
                              void* d_out, int out_size)
{
    const float* article_x   = (const float*)d_in[0];
    const float* community_x = (const float*)d_in[1];
    const int*   e_wb  = (const int*)d_in[2];
    const int*   e_mb  = (const int*)d_in[3];
    const int*   e_int = (const int*)d_in[4];
    const float* W1  = (const float*)d_in[5];
    const float* b1  = (const float*)d_in[6];
    const float* W2  = (const float*)d_in[7];
    const float* b2  = (const float*)d_in[8];
    const float* Wl1 = (const float*)d_in[9];
    const float* bl1 = (const float*)d_in[10];
    const float* Wr1 = (const float*)d_in[11];
    const float* Wl2 = (const float*)d_in[12];
    const float* bl2 = (const float*)d_in[13];
    const float* Wr2 = (const float*)d_in[14];
    const float* Wl3 = (const float*)d_in[15];
    const float* bl3 = (const float*)d_in[16];
    const float* Wr3 = (const float*)d_in[17];
    const float* W3  = (const float*)d_in[18];
    const float* b3  = (const float*)d_in[19];

    const int Ewb  = in_sizes[2] / 2;
    const int Emb  = in_sizes[3] / 2;
    const int Eint = in_sizes[4] / 2;

    float *Wl12T,*Wr1T,*WaT12,*WCR,*Wr2T,*Wl3T,*W3T,*ba12,*bcr;
    float *A12,*CR,*AGG,*CNT,*H1,*H2,*T;
    cudaGetSymbolAddress((void**)&Wl12T, g_Wl12T);
    cudaGetSymbolAddress((void**)&Wr1T,  g_Wr1T);
    cudaGetSymbolAddress((void**)&WaT12, g_WaT12);
    cudaGetSymbolAddress((void**)&WCR,   g_WCR);
    cudaGetSymbolAddress((void**)&Wr2T,  g_Wr2T);
    cudaGetSymbolAddress((void**)&Wl3T,  g_Wl3T);
    cudaGetSymbolAddress((void**)&W3T,   g_W3T);
    cudaGetSymbolAddress((void**)&ba12,  g_ba12);
    cudaGetSymbolAddress((void**)&bcr,   g_bcr);
    cudaGetSymbolAddress((void**)&A12,   g_A12);
    cudaGetSymbolAddress((void**)&CR,    g_CR);
    cudaGetSymbolAddress((void**)&AGG,   g_AGG);
    cudaGetSymbolAddress((void**)&CNT,   g_CNT);
    cudaGetSymbolAddress((void**)&H1,    g_H1);
    cudaGetSymbolAddress((void**)&H2,    g_H2);
    cudaGetSymbolAddress((void**)&T,     g_T);

    const dim3 blk(256);

    // ---- (1) all weight transposes, one launch ----
    transpose_all<<<(TRANS_TOTAL + 255) / 256, blk>>>(
        Wl1, Wl2, Wr1, Wr3, Wr2, Wl3, W3,
        Wl12T, Wr1T, WCR, Wr2T, Wl3T, W3T);

    // ---- (2) folded biases (also zeroes bcr upper half), one launch ----
    dim3 gDot(HID, 3);
    dotrow3_k<<<gDot, blk>>>(b1, b2, Wl12T, Wr1T, ba12, bcr);

    // ---- (3,4) weight folds (tf32-rna; W1/W2 row-major are BT form) ----
    dim3 gF1(FIN/128, 4);  // M=512
    dim3 gF2(FIN/128, 2);  // M=256
    mmagemm<<<gF1, blk>>>(Wl12T, W1, nullptr, WaT12, 2*HID, FIN, PROJ);
    mmagemm<<<gF2, blk>>>(Wr1T,  W2, nullptr, WCR,   HID,   FIN, PROJ);

    // ---- (5,6) node projections, fused N=512 (launch #6 = ncu capture) ----
    dim3 gBig(4, (NART + 127)/128);
    mmagemm<<<gBig, blk>>>(article_x,   WaT12, ba12, A12, NART,  2*HID, FIN);
    mmagemm<<<gBig, blk>>>(community_x, WCR,   bcr,  CR,  NCOMM, 2*HID, FIN);

    const int combBlocks = (NCOMM * (HID/4) + 255)/256;
    dim3 gMid(2, (NCOMM + 127)/128);

    // ---- conv1: h1 = relu(segmean_{e_wb}(A1) + bl1 + C1) ----
    cudaMemsetAsync(AGG, 0, sizeof(float) * NCOMM * HID);
    cudaMemsetAsync(CNT, 0, sizeof(float) * NCOMM);
    scatter_k<<<(Ewb*64 + 255)/256, blk>>>(A12, 2*HID, e_wb, e_wb + Ewb, Ewb, AGG, CNT);
    combine_k<<<combBlocks, blk>>>(AGG, CNT, CR, 2*HID, bl1, H1);

    // ---- conv2: h2 = relu(segmean_{e_mb}(A2) + bl2 + H1@Wr2) ----
    mmagemm<<<gMid, blk>>>(H1, Wr2T, nullptr, T, NCOMM, HID, HID);
    cudaMemsetAsync(AGG, 0, sizeof(float) * NCOMM * HID);
    cudaMemsetAsync(CNT, 0, sizeof(float) * NCOMM);
    scatter_k<<<(Emb*64 + 255)/256, blk>>>(A12 + HID, 2*HID, e_mb, e_mb + Emb, Emb, AGG, CNT);
    combine_k<<<combBlocks, blk>>>(AGG, CNT, T, HID, bl2, H2);

    // ---- conv3: h3 = relu(segmean_{e_int}(H2@Wl3) + bl3 + R3) ----
    mmagemm<<<gMid, blk>>>(H2, Wl3T, nullptr, T, NCOMM, HID, HID);
    cudaMemsetAsync(AGG, 0, sizeof(float) * NCOMM * HID);
    cudaMemsetAsync(CNT, 0, sizeof(float) * NCOMM);
    scatter_k<<<((long)Eint*64 + 255)/256, blk>>>(T, HID, e_int, e_int + Eint, Eint, AGG, CNT);
    combine_k<<<combBlocks, blk>>>(AGG, CNT, CR + HID, 2*HID, bl3, H1);

    // ---- out = H3 @ W3 + b3 ----
    dim3 gOut(1, (NCOMM + 127)/128);
    mmagemm<<<gOut, blk>>>(H1, W3T, b3, (float*)d_out, NCOMM, NOUT, HID);
}

// round 15
// speedup vs baseline: 1.0586x; 1.0586x over previous
#include <cuda_runtime.h>
#include <cstdint>

#define NART  50000
#define NCOMM 50000
#define FIN   768
#define PROJ  1024
#define HID   256
#define NOUT  128

// ---------------- scratch (device globals; no allocation allowed) ----------
__device__ __align__(16) float g_Wl12T[2 * PROJ * HID];   // [Wl1^T ; Wl2^T]  [512,1024]
__device__ __align__(16) float g_Wr1T [PROJ * HID];       // Wr1^T [256,1024]
__device__ __align__(16) float g_WaT12[2 * HID * FIN];    // ([W1@Wl1]^T ; [W1@Wl2]^T) [512,768]
__device__ __align__(16) float g_WCR  [2 * HID * FIN];    // ([W2@Wr1]^T ; Wr3^T)      [512,768]
__device__ __align__(16) float g_Wr2T [HID * HID];
__device__ __align__(16) float g_Wl3T [HID * HID];
__device__ __align__(16) float g_W3T  [NOUT * HID];
__device__ __align__(16) float g_ba12 [2 * HID];          // b1@Wl1 | b1@Wl2
__device__ __align__(16) float g_bcr  [2 * HID];          // b2@Wr1 | 0
__device__ __align__(16) float g_A12  [NART * 2 * HID];   // article proj: A1 | A2
__device__ __align__(16) float g_CR   [NCOMM * 2 * HID];  // community proj: C1 | R3
__device__ __align__(16) float g_AGG  [NCOMM * HID];
__device__ __align__(16) float g_CNT  [NCOMM];
__device__ __align__(16) float g_H1   [NCOMM * HID];      // h1, later h3
__device__ __align__(16) float g_H2   [NCOMM * HID];
__device__ __align__(16) float g_T    [NCOMM * HID];

__device__ __forceinline__ float f2tf32rna(float x) {
    uint32_t r;
    asm("cvt.rna.tf32.f32 %0, %1;" : "=r"(r) : "f"(x));
    return __uint_as_float(r);
}
__device__ __forceinline__ float4 tf32x4(float4 v) {
    v.x = f2tf32rna(v.x); v.y = f2tf32rna(v.y);
    v.z = f2tf32rna(v.z); v.w = f2tf32rna(v.w);
    return v;
}

// ---------------- tf32 mma.sync GEMM: C[M,N] (+)= A[M,K] @ BT[N,K]^T -------
// 128x128 CTA tile, BK=32, 256 threads, warp tile 32x64 (2x8 m16n8k8).
// Static smem, register-prefetch double buffering, rna-rounded staging.
// Split-K via gridDim.z: each z-slice covers K/gridDim.z; when gridDim.z>1
// the epilogue accumulates with vector atomics (C must be pre-zeroed, bias
// must be null). Requires N%128==0, K%(32*gridDim.z)==0; M guarded.
#define PADK 36

__global__ void __launch_bounds__(256) mmagemm(
    const float* __restrict__ A, const float* __restrict__ BT,
    const float* __restrict__ bias, float* __restrict__ C,
    int M, int N, int K)
{
    __shared__ float As[128][PADK];   // rows are 144B = 9*16B -> float4-aligned
    __shared__ float Bs[128][PADK];
    const int tid  = threadIdx.x;
    const int wid  = tid >> 5, lane = tid & 31;
    const int g    = lane >> 2, t = lane & 3;
    const int bm   = blockIdx.y * 128, bn = blockIdx.x * 128;
    const int wm   = (wid >> 1) * 32, wn = (wid & 1) * 64;
    const int nSplit = gridDim.z;
    const int Kc    = K / nSplit;              // per-slice K
    const int kBase = blockIdx.z * Kc;

    float acc[2][8][4];
#pragma unroll
    for (int i = 0; i < 2; ++i)
#pragma unroll
        for (int j = 0; j < 8; ++j)
#pragma unroll
            for (int k = 0; k < 4; ++k) acc[i][j][k] = 0.f;

    // per-thread staging coords: 4 float4 segments each for A and B
    int mIdx[4], kqIdx[4];
#pragma unroll
    for (int s = 0; s < 4; ++s) {
        int i = s * 256 + tid;
        mIdx[s]  = i >> 3;          // 0..127
        kqIdx[s] = (i & 7) * 4;     // 0,4,...,28
    }

    const int nCh = Kc >> 5;
    float4 aReg[4], bReg[4];

    auto fetch = [&](int ci) {
#pragma unroll
        for (int s = 0; s < 4; ++s) {
            const int k0 = kBase + ci * 32 + kqIdx[s];
            const int am = bm + mIdx[s];
            aReg[s] = (am < M) ? *(const float4*)(A + (size_t)am * K + k0)
                               : make_float4(0.f, 0.f, 0.f, 0.f);
            bReg[s] = *(const float4*)(BT + (size_t)(bn + mIdx[s]) * K + k0);
        }
    };

    fetch(0);
    for (int ci = 0; ci < nCh; ++ci) {
#pragma unroll
        for (int s = 0; s < 4; ++s) {
            *(float4*)&As[mIdx[s]][kqIdx[s]] = tf32x4(aReg[s]);
            *(float4*)&Bs[mIdx[s]][kqIdx[s]] = tf32x4(bReg[s]);
        }
        __syncthreads();
        if (ci + 1 < nCh) fetch(ci + 1);   // overlap next LDG with MMA

#pragma unroll
        for (int kk = 0; kk < 32; kk += 8) {
            uint32_t aF[2][4], bF[8][2];
#pragma unroll
            for (int tm = 0; tm < 2; ++tm) {
                int r = wm + tm * 16 + g;
                aF[tm][0] = __float_as_uint(As[r][kk + t]);
                aF[tm][1] = __float_as_uint(As[r + 8][kk + t]);
                aF[tm][2] = __float_as_uint(As[r][kk + t + 4]);
                aF[tm][3] = __float_as_uint(As[r + 8][kk + t + 4]);
            }
#pragma unroll
            for (int tn = 0; tn < 8; ++tn) {
                int c = wn + tn * 8 + g;
                bF[tn][0] = __float_as_uint(Bs[c][kk + t]);
                bF[tn][1] = __float_as_uint(Bs[c][kk + t + 4]);
            }
#pragma unroll
            for (int tm = 0; tm < 2; ++tm)
#pragma unroll
                for (int tn = 0; tn < 8; ++tn)
                    asm volatile(
                        "mma.sync.aligned.m16n8k8.row.col.f32.tf32.tf32.f32 "
                        "{%0,%1,%2,%3}, {%4,%5,%6,%7}, {%8,%9}, {%0,%1,%2,%3};"
                        : "+f"(acc[tm][tn][0]), "+f"(acc[tm][tn][1]),
                          "+f"(acc[tm][tn][2]), "+f"(acc[tm][tn][3])
                        : "r"(aF[tm][0]), "r"(aF[tm][1]), "r"(aF[tm][2]), "r"(aF[tm][3]),
                          "r"(bF[tn][0]), "r"(bF[tn][1]));
        }
        __syncthreads();
    }

    // epilogue: direct store (nSplit==1) or vector-atomic accumulate
#pragma unroll
    for (int tm = 0; tm < 2; ++tm)
#pragma unroll
        for (int half = 0; half < 2; ++half) {
            int row = bm + wm + tm * 16 + g + half * 8;
            if (row >= M) continue;
            float* cr = C + (size_t)row * N + bn + wn;
#pragma unroll
            for (int tn = 0; tn < 8; ++tn) {
                int col = tn * 8 + 2 * t;
                float2 v;
                v.x = acc[tm][tn][half * 2 + 0];
                v.y = acc[tm][tn][half * 2 + 1];
                if (nSplit == 1) {
                    if (bias) {
                        v.x += bias[bn + wn + col];
                        v.y += bias[bn + wn + col + 1];
                    }
                    *(float2*)(cr + col) = v;
                } else {
                    atomicAdd((float2*)(cr + col), v);   // sm_90+: RED.E.ADD.F32.V2
                }
            }
        }
}

// ---------------- fused prelude: all 7 weight transposes in one launch ------
__global__ void __launch_bounds__(256) transpose_all(
    const float* __restrict__ Wl1, const float* __restrict__ Wl2,
    const float* __restrict__ Wr1, const float* __restrict__ Wr3,
    const float* __restrict__ Wr2, const float* __restrict__ Wl3,
    const float* __restrict__ W3,
    float* __restrict__ Wl12T, float* __restrict__ Wr1T, float* __restrict__ WCR,
    float* __restrict__ Wr2T, float* __restrict__ Wl3T, float* __restrict__ W3T)
{
    int t = blockIdx.x * blockDim.x + threadIdx.x;
    const int S1 = PROJ * HID;   // 262144
    const int S4 = FIN * HID;    // 196608
    const int S5 = HID * HID;    // 65536
    const int S7 = HID * NOUT;   // 32768
    if (t < S1) {                                   // Wl1 -> Wl12T rows 0-255
        int r = t / HID, c = t % HID;
        Wl12T[(size_t)c * PROJ + r] = Wl1[t];
    } else if ((t -= S1) < S1) {                    // Wl2 -> Wl12T rows 256-511
        int r = t / HID, c = t % HID;
        Wl12T[S1 + (size_t)c * PROJ + r] = Wl2[t];
    } else if ((t -= S1) < S1) {                    // Wr1 -> Wr1T
        int r = t / HID, c = t % HID;
        Wr1T[(size_t)c * PROJ + r] = Wr1[t];
    } else if ((t -= S1) < S4) {                    // Wr3 -> WCR rows 256-511
        int r = t / HID, c = t % HID;
        WCR[(size_t)HID * FIN + (size_t)c * FIN + r] = Wr3[t];
    } else if ((t -= S4) < S5) {                    // Wr2 -> Wr2T
        int r = t / HID, c = t % HID;
        Wr2T[(size_t)c * HID + r] = Wr2[t];
    } else if ((t -= S5) < S5) {                    // Wl3 -> Wl3T
        int r = t / HID, c = t % HID;
        Wl3T[(size_t)c * HID + r] = Wl3[t];
    } else if ((t -= S5) < S7) {                    // W3 -> W3T
        int r = t / NOUT, c = t % NOUT;
        W3T[(size_t)c * HID + r] = W3[t];
    }
}
#define TRANS_TOTAL (3 * PROJ * HID + FIN * HID + 2 * HID * HID + HID * NOUT)

// ---------------- fused bias folds: 3 vec@mat in one launch -----------------
__global__ void __launch_bounds__(256) dotrow3_k(
    const float* __restrict__ b1, const float* __restrict__ b2,
    const float* __restrict__ Wl12T, const float* __restrict__ Wr1T,
    float* __restrict__ ba12, float* __restrict__ bcr)
{
    const int j = blockIdx.y, c = blockIdx.x, tid = threadIdx.x;
    const float* v;
    const float* row;
    float* out;
    if (j == 0)      { v = b1; row = Wl12T + (size_t)c * PROJ;         out = ba12 + c; }
    else if (j == 1) { v = b1; row = Wl12T + (size_t)(HID + c) * PROJ; out = ba12 + HID + c; }
    else             { v = b2; row = Wr1T  + (size_t)c * PROJ;         out = bcr + c;
                       if (tid == 0) bcr[HID + c] = 0.f; }
    float s = 0.f;
    for (int k = tid; k < PROJ; k += 256) s = fmaf(row[k], v[k], s);
#pragma unroll
    for (int o = 16; o > 0; o >>= 1) s += __shfl_xor_sync(0xFFFFFFFFu, s, o);
    __shared__ float red[8];
    if ((tid & 31) == 0) red[tid >> 5] = s;
    __syncthreads();
    if (tid == 0) {
        float r = red[0];
#pragma unroll
        for (int w = 1; w < 8; ++w) r += red[w];
        *out = r;
    }
}

// agg[dst,:HID] += feat[src*ld : +HID]; cnt[dst] += 1 (lane 0 of each edge).
__global__ void scatter_k(const float* __restrict__ feat, int ld,
                          const int* __restrict__ src, const int* __restrict__ dst,
                          int E, float* __restrict__ agg, float* __restrict__ cnt)
{
    int tt = blockIdx.x * blockDim.x + threadIdx.x;
    int e = tt >> 6;
    if (e >= E) return;
    int c4 = (tt & 63) * 4;
    int d = dst[e];
    float4 v = *(const float4*)(feat + (size_t)src[e] * ld + c4);
    float4* o = (float4*)(agg + (size_t)d * HID + c4);
    atomicAdd(o, v);   // sm_90+: RED.E.ADD.F32.V4
    if ((tt & 63) == 0) atomicAdd(cnt + d, 1.0f);
}

// out = relu(agg/max(cnt,1) + bias + other)  (other has leading dim ldO)
__global__ void combine_k(const float* __restrict__ agg, const float* __restrict__ cnt,
                          const float* __restrict__ other, int ldO,
                          const float* __restrict__ bias, float* __restrict__ out)
{
    int t = blockIdx.x * blockDim.x + threadIdx.x;
    if (t >= NCOMM * (HID / 4)) return;
    int i = t >> 6;
    int c4 = (t & 63) * 4;
    float inv = 1.0f / fmaxf(cnt[i], 1.0f);
    float4 a = *(const float4*)(agg + (size_t)i * HID + c4);
    float4 o = *(const float4*)(other + (size_t)i * ldO + c4);
    float4 b = *(const float4*)(bias + c4);
    float4 r;
    r.x = fmaxf(fmaf(a.x, inv, o.x + b.x), 0.f);
    r.y = fmaxf(fmaf(a.y, inv, o.y + b.y), 0.f);
    r.z = fmaxf(fmaf(a.z, inv, o.z + b.z), 0.f);
    r.w = fmaxf(fmaf(a.w, inv, o.w + b.w), 0.f);
    *(float4*)(out + (size_t)i * HID + c4) = r;
}

// ---------------- launch ----------------------------------------------------
extern "C" void kernel_launch(void* const* d_in, const int* in_sizes, int n_in,
                              void* d_out, int out_size)
{
    const float* article_x   = (const float*)d_in[0];
    const float* community_x = (const float*)d_in[1];
    const int*   e_wb  = (const int*)d_in[2];
    const int*   e_mb  = (const int*)d_in[3];
    const int*   e_int = (const int*)d_in[4];
    const float* W1  = (const float*)d_in[5];
    const float* b1  = (const float*)d_in[6];
    const float* W2  = (const float*)d_in[7];
    const float* b2  = (const float*)d_in[8];
    const float* Wl1 = (const float*)d_in[9];
    const float* bl1 = (const float*)d_in[10];
    const float* Wr1 = (const float*)d_in[11];
    const float* Wl2 = (const float*)d_in[12];
    const float* bl2 = (const float*)d_in[13];
    const float* Wr2 = (const float*)d_in[14];
    const float* Wl3 = (const float*)d_in[15];
    const float* bl3 = (const float*)d_in[16];
    const float* Wr3 = (const float*)d_in[17];
    const float* W3  = (const float*)d_in[18];
    const float* b3  = (const float*)d_in[19];

    const int Ewb  = in_sizes[2] / 2;
    const int Emb  = in_sizes[3] / 2;
    const int Eint = in_sizes[4] / 2;

    float *Wl12T,*Wr1T,*WaT12,*WCR,*Wr2T,*Wl3T,*W3T,*ba12,*bcr;
    float *A12,*CR,*AGG,*CNT,*H1,*H2,*T;
    cudaGetSymbolAddress((void**)&Wl12T, g_Wl12T);
    cudaGetSymbolAddress((void**)&Wr1T,  g_Wr1T);
    cudaGetSymbolAddress((void**)&WaT12, g_WaT12);
    cudaGetSymbolAddress((void**)&WCR,   g_WCR);
    cudaGetSymbolAddress((void**)&Wr2T,  g_Wr2T);
    cudaGetSymbolAddress((void**)&Wl3T,  g_Wl3T);
    cudaGetSymbolAddress((void**)&W3T,   g_W3T);
    cudaGetSymbolAddress((void**)&ba12,  g_ba12);
    cudaGetSymbolAddress((void**)&bcr,   g_bcr);
    cudaGetSymbolAddress((void**)&A12,   g_A12);
    cudaGetSymbolAddress((void**)&CR,    g_CR);
    cudaGetSymbolAddress((void**)&AGG,   g_AGG);
    cudaGetSymbolAddress((void**)&CNT,   g_CNT);
    cudaGetSymbolAddress((void**)&H1,    g_H1);
    cudaGetSymbolAddress((void**)&H2,    g_H2);
    cudaGetSymbolAddress((void**)&T,     g_T);

    const dim3 blk(256);

    // ---- (1) all weight transposes, one launch ----
    transpose_all<<<(TRANS_TOTAL + 255) / 256, blk>>>(
        Wl1, Wl2, Wr1, Wr3, Wr2, Wl3, W3,
        Wl12T, Wr1T, WCR, Wr2T, Wl3T, W3T);

    // ---- (2) folded biases (also zeroes bcr upper half), one launch ----
    dim3 gDot(HID, 3);
    dotrow3_k<<<gDot, blk>>>(b1, b2, Wl12T, Wr1T, ba12, bcr);

    // ---- (3,4) weight folds: split-K=4 tf32 GEMMs into pre-zeroed outputs --
    cudaMemsetAsync(WaT12, 0, sizeof(float) * 2 * HID * FIN);
    cudaMemsetAsync(WCR,   0, sizeof(float) * HID * FIN);   // rows 0-255 only (rows 256+ = Wr3^T)
    dim3 gF1(FIN/128, 4, 4);  // M=512, K split 4x256
    dim3 gF2(FIN/128, 2, 4);  // M=256
    mmagemm<<<gF1, blk>>>(Wl12T, W1, nullptr, WaT12, 2*HID, FIN, PROJ);
    mmagemm<<<gF2, blk>>>(Wr1T,  W2, nullptr, WCR,   HID,   FIN, PROJ);

    // ---- (5,6) node projections, fused N=512 ----
    dim3 gBig(4, (NART + 127)/128);
    mmagemm<<<gBig, blk>>>(article_x,   WaT12, ba12, A12, NART,  2*HID, FIN);
    mmagemm<<<gBig, blk>>>(community_x, WCR,   bcr,  CR,  NCOMM, 2*HID, FIN);

    const int combBlocks = (NCOMM * (HID/4) + 255)/256;
    dim3 gMid(2, (NCOMM + 127)/128);

    // ---- conv1: h1 = relu(segmean_{e_wb}(A1) + bl1 + C1) ----
    cudaMemsetAsync(AGG, 0, sizeof(float) * NCOMM * HID);
    cudaMemsetAsync(CNT, 0, sizeof(float) * NCOMM);
    scatter_k<<<(Ewb*64 + 255)/256, blk>>>(A12, 2*HID, e_wb, e_wb + Ewb, Ewb, AGG, CNT);
    combine_k<<<combBlocks, blk>>>(AGG, CNT, CR, 2*HID, bl1, H1);

    // ---- conv2: h2 = relu(segmean_{e_mb}(A2) + bl2 + H1@Wr2) ----
    mmagemm<<<gMid, blk>>>(H1, Wr2T, nullptr, T, NCOMM, HID, HID);
    cudaMemsetAsync(AGG, 0, sizeof(float) * NCOMM * HID);
    cudaMemsetAsync(CNT, 0, sizeof(float) * NCOMM);
    scatter_k<<<(Emb*64 + 255)/256, blk>>>(A12 + HID, 2*HID, e_mb, e_mb + Emb, Emb, AGG, CNT);
    combine_k<<<combBlocks, blk>>>(AGG, CNT, T, HID, bl2, H2);

    // ---- conv3: h3 = relu(segmean_{e_int}(H2@Wl3) + bl3 + R3) ----
    mmagemm<<<gMid, blk>>>(H2, Wl3T, nullptr, T, NCOMM, HID, HID);
    cudaMemsetAsync(AGG, 0, sizeof(float) * NCOMM * HID);
    cudaMemsetAsync(CNT, 0, sizeof(float) * NCOMM);
    scatter_k<<<((long)Eint*64 + 255)/256, blk>>>(T, HID, e_int, e_int + Eint, Eint, AGG, CNT);
    combine_k<<<combBlocks, blk>>>(AGG, CNT, CR + HID, 2*HID, bl3, H1);

    // ---- out = H3 @ W3 + b3 ----
    dim3 gOut(1, (NCOMM + 127)/128);
    mmagemm<<<gOut, blk>>>(H1, W3T, b3, (float*)d_out, NCOMM, NOUT, HID);
}

// round 16
// speedup vs baseline: 1.0783x; 1.0186x over previous
#include <cuda_runtime.h>
#include <cstdint>

#define NART  50000
#define NCOMM 50000
#define FIN   768
#define PROJ  1024
#define HID   256
#define NOUT  128

// ---------------- scratch (device globals; no allocation allowed) ----------
__device__ __align__(16) float g_Wl12T[2 * PROJ * HID];   // [Wl1^T ; Wl2^T]  [512,1024]
__device__ __align__(16) float g_Wr1T [PROJ * HID];       // Wr1^T [256,1024]
__device__ __align__(16) float g_WaT12[2 * HID * FIN];    // ([W1@Wl1]^T ; [W1@Wl2]^T) [512,768]
__device__ __align__(16) float g_WCR  [2 * HID * FIN];    // ([W2@Wr1]^T ; Wr3^T)      [512,768]
__device__ __align__(16) float g_Wr2T [HID * HID];
__device__ __align__(16) float g_Wl3T [HID * HID];
__device__ __align__(16) float g_W3T  [NOUT * HID];
__device__ __align__(16) float g_ba12 [2 * HID];          // b1@Wl1 | b1@Wl2
__device__ __align__(16) float g_bcr  [2 * HID];          // b2@Wr1 | 0
__device__ __align__(16) float g_A12  [NART * 2 * HID];   // article proj: A1 | A2
__device__ __align__(16) float g_CR   [NCOMM * 2 * HID];  // community proj: C1 | R3
__device__ __align__(16) float g_AGG  [NCOMM * HID];      // zero at entry (invariant)
__device__ __align__(16) float g_CNT  [NCOMM];            // zero at entry (invariant)
__device__ __align__(16) float g_H1   [NCOMM * HID];      // h1, later h3
__device__ __align__(16) float g_H2   [NCOMM * HID];
__device__ __align__(16) float g_T    [NCOMM * HID];

__device__ __forceinline__ float f2tf32rna(float x) {
    uint32_t r;
    asm("cvt.rna.tf32.f32 %0, %1;" : "=r"(r) : "f"(x));
    return __uint_as_float(r);
}
__device__ __forceinline__ float4 tf32x4(float4 v) {
    v.x = f2tf32rna(v.x); v.y = f2tf32rna(v.y);
    v.z = f2tf32rna(v.z); v.w = f2tf32rna(v.w);
    return v;
}

// ---------------- tf32 mma.sync GEMM: C[M,N] (+)= A[M,K] @ BT[N,K]^T -------
// 128x128 CTA tile, BK=32, 256 threads, warp tile 32x64 (2x8 m16n8k8).
// Fragment loads via ldmatrix.m8n8.x4 (6 LDSM vs 24 LDS per kk-step).
// Split-K via gridDim.z (atomic accumulate into pre-zeroed C; bias null).
// Requires N%128==0, K%(32*gridDim.z)==0; M guarded.
#define PADK 36

__global__ void __launch_bounds__(256) mmagemm(
    const float* __restrict__ A, const float* __restrict__ BT,
    const float* __restrict__ bias, float* __restrict__ C,
    int M, int N, int K)
{
    __shared__ __align__(16) float As[128][PADK];   // row = 144B = 9*16B
    __shared__ __align__(16) float Bs[128][PADK];
    const int tid  = threadIdx.x;
    const int wid  = tid >> 5, lane = tid & 31;
    const int g    = lane >> 2, t = lane & 3;
    const int bm   = blockIdx.y * 128, bn = blockIdx.x * 128;
    const int wm   = (wid >> 1) * 32, wn = (wid & 1) * 64;
    const int nSplit = gridDim.z;
    const int Kc    = K / nSplit;
    const int kBase = blockIdx.z * Kc;

    float acc[2][8][4];
#pragma unroll
    for (int i = 0; i < 2; ++i)
#pragma unroll
        for (int j = 0; j < 8; ++j)
#pragma unroll
            for (int k = 0; k < 4; ++k) acc[i][j][k] = 0.f;

    // ldmatrix per-lane source addresses (fixed; +kk*4 bytes per step)
    const int l8 = lane & 7, l16 = (lane >> 3) & 1, l32 = lane >> 4;
    const uint32_t sA = (uint32_t)__cvta_generic_to_shared(&As[0][0]);
    const uint32_t sB = (uint32_t)__cvta_generic_to_shared(&Bs[0][0]);
    uint32_t aAddr[2], bAddr[4];
#pragma unroll
    for (int tm = 0; tm < 2; ++tm)
        aAddr[tm] = sA + (uint32_t)(((wm + tm * 16 + l8 + 8 * l16) * PADK + 4 * l32) * 4);
#pragma unroll
    for (int p = 0; p < 4; ++p)
        bAddr[p] = sB + (uint32_t)(((wn + (2 * p + l32) * 8 + l8) * PADK + 4 * l16) * 4);

    // per-thread staging coords: 4 float4 segments each for A and B
    int mIdx[4], kqIdx[4];
#pragma unroll
    for (int s = 0; s < 4; ++s) {
        int i = s * 256 + tid;
        mIdx[s]  = i >> 3;          // 0..127
        kqIdx[s] = (i & 7) * 4;     // 0,4,...,28
    }

    const int nCh = Kc >> 5;
    float4 aReg[4], bReg[4];

    auto fetch = [&](int ci) {
#pragma unroll
        for (int s = 0; s < 4; ++s) {
            const int k0 = kBase + ci * 32 + kqIdx[s];
            const int am = bm + mIdx[s];
            aReg[s] = (am < M) ? *(const float4*)(A + (size_t)am * K + k0)
                               : make_float4(0.f, 0.f, 0.f, 0.f);
            bReg[s] = *(const float4*)(BT + (size_t)(bn + mIdx[s]) * K + k0);
        }
    };

    fetch(0);
    for (int ci = 0; ci < nCh; ++ci) {
#pragma unroll
        for (int s = 0; s < 4; ++s) {
            *(float4*)&As[mIdx[s]][kqIdx[s]] = tf32x4(aReg[s]);
            *(float4*)&Bs[mIdx[s]][kqIdx[s]] = tf32x4(bReg[s]);
        }
        __syncthreads();
        if (ci + 1 < nCh) fetch(ci + 1);   // overlap next LDG with MMA

#pragma unroll
        for (int kk = 0; kk < 32; kk += 8) {
            uint32_t aF[2][4], bF[8][2];
#pragma unroll
            for (int tm = 0; tm < 2; ++tm)
                asm volatile(
                    "ldmatrix.sync.aligned.m8n8.x4.shared.b16 {%0,%1,%2,%3}, [%4];"
                    : "=r"(aF[tm][0]), "=r"(aF[tm][1]),
                      "=r"(aF[tm][2]), "=r"(aF[tm][3])
                    : "r"(aAddr[tm] + (uint32_t)(kk * 4)));
#pragma unroll
            for (int p = 0; p < 4; ++p)
                asm volatile(
                    "ldmatrix.sync.aligned.m8n8.x4.shared.b16 {%0,%1,%2,%3}, [%4];"
                    : "=r"(bF[2 * p][0]), "=r"(bF[2 * p][1]),
                      "=r"(bF[2 * p + 1][0]), "=r"(bF[2 * p + 1][1])
                    : "r"(bAddr[p] + (uint32_t)(kk * 4)));
#pragma unroll
            for (int tm = 0; tm < 2; ++tm)
#pragma unroll
                for (int tn = 0; tn < 8; ++tn)
                    asm volatile(
                        "mma.sync.aligned.m16n8k8.row.col.f32.tf32.tf32.f32 "
                        "{%0,%1,%2,%3}, {%4,%5,%6,%7}, {%8,%9}, {%0,%1,%2,%3};"
                        : "+f"(acc[tm][tn][0]), "+f"(acc[tm][tn][1]),
                          "+f"(acc[tm][tn][2]), "+f"(acc[tm][tn][3])
                        : "r"(aF[tm][0]), "r"(aF[tm][1]), "r"(aF[tm][2]), "r"(aF[tm][3]),
                          "r"(bF[tn][0]), "r"(bF[tn][1]));
        }
        __syncthreads();
    }

    // epilogue: direct store (nSplit==1) or vector-atomic accumulate
#pragma unroll
    for (int tm = 0; tm < 2; ++tm)
#pragma unroll
        for (int half = 0; half < 2; ++half) {
            int row = bm + wm + tm * 16 + g + half * 8;
            if (row >= M) continue;
            float* cr = C + (size_t)row * N + bn + wn;
#pragma unroll
            for (int tn = 0; tn < 8; ++tn) {
                int col = tn * 8 + 2 * t;
                float2 v;
                v.x = acc[tm][tn][half * 2 + 0];
                v.y = acc[tm][tn][half * 2 + 1];
                if (nSplit == 1) {
                    if (bias) {
                        v.x += bias[bn + wn + col];
                        v.y += bias[bn + wn + col + 1];
                    }
                    *(float2*)(cr + col) = v;
                } else {
                    atomicAdd((float2*)(cr + col), v);   // sm_90+: RED.E.ADD.F32.V2
                }
            }
        }
}

// ---------------- fused prelude: all 7 weight transposes in one launch ------
__global__ void __launch_bounds__(256) transpose_all(
    const float* __restrict__ Wl1, const float* __restrict__ Wl2,
    const float* __restrict__ Wr1, const float* __restrict__ Wr3,
    const float* __restrict__ Wr2, const float* __restrict__ Wl3,
    const float* __restrict__ W3,
    float* __restrict__ Wl12T, float* __restrict__ Wr1T, float* __restrict__ WCR,
    float* __restrict__ Wr2T, float* __restrict__ Wl3T, float* __restrict__ W3T)
{
    int t = blockIdx.x * blockDim.x + threadIdx.x;
    const int S1 = PROJ * HID;
    const int S4 = FIN * HID;
    const int S5 = HID * HID;
    const int S7 = HID * NOUT;
    if (t < S1) {
        int r = t / HID, c = t % HID;
        Wl12T[(size_t)c * PROJ + r] = Wl1[t];
    } else if ((t -= S1) < S1) {
        int r = t / HID, c = t % HID;
        Wl12T[S1 + (size_t)c * PROJ + r] = Wl2[t];
    } else if ((t -= S1) < S1) {
        int r = t / HID, c = t % HID;
        Wr1T[(size_t)c * PROJ + r] = Wr1[t];
    } else if ((t -= S1) < S4) {
        int r = t / HID, c = t % HID;
        WCR[(size_t)HID * FIN + (size_t)c * FIN + r] = Wr3[t];
    } else if ((t -= S4) < S5) {
        int r = t / HID, c = t % HID;
        Wr2T[(size_t)c * HID + r] = Wr2[t];
    } else if ((t -= S5) < S5) {
        int r = t / HID, c = t % HID;
        Wl3T[(size_t)c * HID + r] = Wl3[t];
    } else if ((t -= S5) < S7) {
        int r = t / NOUT, c = t % NOUT;
        W3T[(size_t)c * HID + r] = W3[t];
    }
}
#define TRANS_TOTAL (3 * PROJ * HID + FIN * HID + 2 * HID * HID + HID * NOUT)

// ---------------- fused bias folds: 3 vec@mat in one launch -----------------
__global__ void __launch_bounds__(256) dotrow3_k(
    const float* __restrict__ b1, const float* __restrict__ b2,
    const float* __restrict__ Wl12T, const float* __restrict__ Wr1T,
    float* __restrict__ ba12, float* __restrict__ bcr)
{
    const int j = blockIdx.y, c = blockIdx.x, tid = threadIdx.x;
    const float* v;
    const float* row;
    float* out;
    if (j == 0)      { v = b1; row = Wl12T + (size_t)c * PROJ;         out = ba12 + c; }
    else if (j == 1) { v = b1; row = Wl12T + (size_t)(HID + c) * PROJ; out = ba12 + HID + c; }
    else             { v = b2; row = Wr1T  + (size_t)c * PROJ;         out = bcr + c;
                       if (tid == 0) bcr[HID + c] = 0.f; }
    float s = 0.f;
    for (int k = tid; k < PROJ; k += 256) s = fmaf(row[k], v[k], s);
#pragma unroll
    for (int o = 16; o > 0; o >>= 1) s += __shfl_xor_sync(0xFFFFFFFFu, s, o);
    __shared__ float red[8];
    if ((tid & 31) == 0) red[tid >> 5] = s;
    __syncthreads();
    if (tid == 0) {
        float r = red[0];
#pragma unroll
        for (int w = 1; w < 8; ++w) r += red[w];
        *out = r;
    }
}

// agg[dst,:HID] += feat[src*ld : +HID]; cnt[dst] += 1 (lane 0 of each edge).
__global__ void scatter_k(const float* __restrict__ feat, int ld,
                          const int* __restrict__ src, const int* __restrict__ dst,
                          int E, float* __restrict__ agg, float* __restrict__ cnt)
{
    int tt = blockIdx.x * blockDim.x + threadIdx.x;
    int e = tt >> 6;
    if (e >= E) return;
    int c4 = (tt & 63) * 4;
    int d = dst[e];
    float4 v = *(const float4*)(feat + (size_t)src[e] * ld + c4);
    float4* o = (float4*)(agg + (size_t)d * HID + c4);
    atomicAdd(o, v);   // sm_90+: RED.E.ADD.F32.V4
    if ((tt & 63) == 0) atomicAdd(cnt + d, 1.0f);
}

// out = relu(agg/max(cnt,1) + bias + other); then restore agg/cnt to ZERO
// (replaces the per-conv memsets; invariant: AGG/CNT zero at kernel entry).
// Grid is exact: NCOMM*64 threads / 256 — no partial blocks, barrier is safe.
__global__ void combine_k(float* __restrict__ agg, float* __restrict__ cnt,
                          const float* __restrict__ other, int ldO,
                          const float* __restrict__ bias, float* __restrict__ out)
{
    int t = blockIdx.x * blockDim.x + threadIdx.x;
    int i = t >> 6;
    int c4 = (t & 63) * 4;
    float cv = cnt[i];
    float4 a = *(const float4*)(agg + (size_t)i * HID + c4);
    __syncthreads();                       // all reads of cnt/agg done
    if ((t & 63) == 0) cnt[i] = 0.f;
    *(float4*)(agg + (size_t)i * HID + c4) = make_float4(0.f, 0.f, 0.f, 0.f);
    float inv = 1.0f / fmaxf(cv, 1.0f);
    float4 o = *(const float4*)(other + (size_t)i * ldO + c4);
    float4 b = *(const float4*)(bias + c4);
    float4 r;
    r.x = fmaxf(fmaf(a.x, inv, o.x + b.x), 0.f);
    r.y = fmaxf(fmaf(a.y, inv, o.y + b.y), 0.f);
    r.z = fmaxf(fmaf(a.z, inv, o.z + b.z), 0.f);
    r.w = fmaxf(fmaf(a.w, inv, o.w + b.w), 0.f);
    *(float4*)(out + (size_t)i * HID + c4) = r;
}

// ---------------- launch ----------------------------------------------------
extern "C" void kernel_launch(void* const* d_in, const int* in_sizes, int n_in,
                              void* d_out, int out_size)
{
    const float* article_x   = (const float*)d_in[0];
    const float* community_x = (const float*)d_in[1];
    const int*   e_wb  = (const int*)d_in[2];
    const int*   e_mb  = (const int*)d_in[3];
    const int*   e_int = (const int*)d_in[4];
    const float* W1  = (const float*)d_in[5];
    const float* b1  = (const float*)d_in[6];
    const float* W2  = (const float*)d_in[7];
    const float* b2  = (const float*)d_in[8];
    const float* Wl1 = (const float*)d_in[9];
    const float* bl1 = (const float*)d_in[10];
    const float* Wr1 = (const float*)d_in[11];
    const float* Wl2 = (const float*)d_in[12];
    const float* bl2 = (const float*)d_in[13];
    const float* Wr2 = (const float*)d_in[14];
    const float* Wl3 = (const float*)d_in[15];
    const float* bl3 = (const float*)d_in[16];
    const float* Wr3 = (const float*)d_in[17];
    const float* W3  = (const float*)d_in[18];
    const float* b3  = (const float*)d_in[19];

    const int Ewb  = in_sizes[2] / 2;
    const int Emb  = in_sizes[3] / 2;
    const int Eint = in_sizes[4] / 2;

    float *Wl12T,*Wr1T,*WaT12,*WCR,*Wr2T,*Wl3T,*W3T,*ba12,*bcr;
    float *A12,*CR,*AGG,*CNT,*H1,*H2,*T;
    cudaGetSymbolAddress((void**)&Wl12T, g_Wl12T);
    cudaGetSymbolAddress((void**)&Wr1T,  g_Wr1T);
    cudaGetSymbolAddress((void**)&WaT12, g_WaT12);
    cudaGetSymbolAddress((void**)&WCR,   g_WCR);
    cudaGetSymbolAddress((void**)&Wr2T,  g_Wr2T);
    cudaGetSymbolAddress((void**)&Wl3T,  g_Wl3T);
    cudaGetSymbolAddress((void**)&W3T,   g_W3T);
    cudaGetSymbolAddress((void**)&ba12,  g_ba12);
    cudaGetSymbolAddress((void**)&bcr,   g_bcr);
    cudaGetSymbolAddress((void**)&A12,   g_A12);
    cudaGetSymbolAddress((void**)&CR,    g_CR);
    cudaGetSymbolAddress((void**)&AGG,   g_AGG);
    cudaGetSymbolAddress((void**)&CNT,   g_CNT);
    cudaGetSymbolAddress((void**)&H1,    g_H1);
    cudaGetSymbolAddress((void**)&H2,    g_H2);
    cudaGetSymbolAddress((void**)&T,     g_T);

    const dim3 blk(256);

    // ---- (1,2) zero split-K fold outputs (accumulated atomically each call)
    cudaMemsetAsync(WaT12, 0, sizeof(float) * 2 * HID * FIN);
    cudaMemsetAsync(WCR,   0, sizeof(float) * HID * FIN);   // rows 0-255 only

    // ---- (3) all weight transposes, one launch ----
    transpose_all<<<(TRANS_TOTAL + 255) / 256, blk>>>(
        Wl1, Wl2, Wr1, Wr3, Wr2, Wl3, W3,
        Wl12T, Wr1T, WCR, Wr2T, Wl3T, W3T);

    // ---- (4) folded biases, one launch ----
    dim3 gDot(HID, 3);
    dotrow3_k<<<gDot, blk>>>(b1, b2, Wl12T, Wr1T, ba12, bcr);

    // ---- (5) fold1 (split-K=4), (6) article projection [ncu capture target]
    dim3 gF1(FIN/128, 4, 4);
    dim3 gBig(4, (NART + 127)/128);
    mmagemm<<<gF1, blk>>>(Wl12T, W1, nullptr, WaT12, 2*HID, FIN, PROJ);
    mmagemm<<<gBig, blk>>>(article_x, WaT12, ba12, A12, NART, 2*HID, FIN);

    // ---- (7) fold2, (8) community projection ----
    dim3 gF2(FIN/128, 2, 4);
    mmagemm<<<gF2, blk>>>(Wr1T, W2, nullptr, WCR, HID, FIN, PROJ);
    mmagemm<<<gBig, blk>>>(community_x, WCR, bcr, CR, NCOMM, 2*HID, FIN);

    const int combBlocks = NCOMM * (HID / 4) / 256;   // exact division
    dim3 gMid(2, (NCOMM + 127)/128);

    // ---- conv1: h1 = relu(segmean_{e_wb}(A1) + bl1 + C1) ----
    scatter_k<<<(Ewb*64 + 255)/256, blk>>>(A12, 2*HID, e_wb, e_wb + Ewb, Ewb, AGG, CNT);
    combine_k<<<combBlocks, blk>>>(AGG, CNT, CR, 2*HID, bl1, H1);

    // ---- conv2: h2 = relu(segmean_{e_mb}(A2) + bl2 + H1@Wr2) ----
    mmagemm<<<gMid, blk>>>(H1, Wr2T, nullptr, T, NCOMM, HID, HID);
    scatter_k<<<(Emb*64 + 255)/256, blk>>>(A12 + HID, 2*HID, e_mb, e_mb + Emb, Emb, AGG, CNT);
    combine_k<<<combBlocks, blk>>>(AGG, CNT, T, HID, bl2, H2);

    // ---- conv3: h3 = relu(segmean_{e_int}(H2@Wl3) + bl3 + R3) ----
    mmagemm<<<gMid, blk>>>(H2, Wl3T, nullptr, T, NCOMM, HID, HID);
    scatter_k<<<((long)Eint*64 + 255)/256, blk>>>(T, HID, e_int, e_int + Eint, Eint, AGG, CNT);
    combine_k<<<combBlocks, blk>>>(AGG, CNT, CR + HID, 2*HID, bl3, H1);

    // ---- out = H3 @ W3 + b3 ----
    dim3 gOut(1, (NCOMM + 127)/128);
    mmagemm<<<gOut, blk>>>(H1, W3T, b3, (float*)d_out, NCOMM, NOUT, HID);
}